// round 10
// baseline (speedup 1.0000x reference)
#include <cuda_runtime.h>
#include <cuda_bf16.h>
#include <mma.h>
#include <cstdint>

using namespace nvcuda;

#define T_TOK   2048
#define IDIM_   1024
#define HIDDEN_ 4096
#define NEXP    8

// Feature gate: tcgen05 PTX is only legal when the device pass targets an
// arch-specific ('a') Blackwell target. compute_103 (no 'a') must compile it out.
#if !defined(__CUDA_ARCH__) || defined(__CUDA_ARCH_FEAT_SM103_ALL) || \
    defined(__CUDA_ARCH_FEAT_SM100_ALL) || defined(__CUDA_ARCH_SPECIFIC__)
#define TC_PATH 1
#else
#define TC_PATH 0
#endif

// ---- device scratch (allocation-free: static device globals) ----
__device__ int   g_count[NEXP];
__device__ int   g_offset[NEXP];
__device__ int   g_tok[NEXP][T_TOK];
__device__ float g_w[NEXP][T_TOK];
__device__ float g_h[(size_t)2 * T_TOK * HIDDEN_];   // compacted hidden rows
__device__ int   g_use_tc;                            // runtime dispatch flag

// ---------------------------------------------------------------
__global__ void probe_kernel() {
    if (threadIdx.x == 0) {
#if TC_PATH && defined(__CUDA_ARCH__)
        g_use_tc = 1;
#else
        g_use_tc = 0;
#endif
    }
    if (threadIdx.x < NEXP) g_count[threadIdx.x] = 0;
}

__global__ void router_kernel(const float* __restrict__ xs,
                              const float* __restrict__ Wg) {
    int gwarp = (blockIdx.x * blockDim.x + threadIdx.x) >> 5;
    int lane  = threadIdx.x & 31;
    if (gwarp >= T_TOK) return;
    const float4* x = (const float4*)(xs + (size_t)gwarp * IDIM_);
    float acc[NEXP];
#pragma unroll
    for (int e = 0; e < NEXP; e++) acc[e] = 0.f;
    for (int k = lane; k < IDIM_ / 4; k += 32) {
        float4 xv = x[k];
#pragma unroll
        for (int e = 0; e < NEXP; e++) {
            const float4 wv = ((const float4*)(Wg + e * IDIM_))[k];
            acc[e] += xv.x * wv.x + xv.y * wv.y + xv.z * wv.z + xv.w * wv.w;
        }
    }
#pragma unroll
    for (int e = 0; e < NEXP; e++)
#pragma unroll
        for (int off = 16; off; off >>= 1)
            acc[e] += __shfl_xor_sync(0xffffffffu, acc[e], off);
    if (lane == 0) {
        int i0 = 0; float v0 = acc[0];
#pragma unroll
        for (int e = 1; e < NEXP; e++) if (acc[e] > v0) { v0 = acc[e]; i0 = e; }
        int i1 = -1; float v1 = -3.4e38f;
#pragma unroll
        for (int e = 0; e < NEXP; e++) if (e != i0 && acc[e] > v1) { v1 = acc[e]; i1 = e; }
        float e1 = expf(v1 - v0);
        float s  = 1.0f + e1;
        int s0 = atomicAdd(&g_count[i0], 1);
        g_tok[i0][s0] = gwarp; g_w[i0][s0] = 1.0f / s;
        int s1 = atomicAdd(&g_count[i1], 1);
        g_tok[i1][s1] = gwarp; g_w[i1][s1] = e1 / s;
    }
}

__global__ void compute_offsets_kernel() {
    if (threadIdx.x == 0) {
        int off = 0;
#pragma unroll
        for (int e = 0; e < NEXP; e++) { g_offset[e] = off; off += g_count[e]; }
    }
}

// ===============================================================
// Path A: wmma tf32 fallback (self-disables when g_use_tc == 1).
// ===============================================================
#define WBM 128
#define WBN 128
#define WBK 16
#define WAS_STRIDE 20
#define WAS_TILE   (WBM * WAS_STRIDE)
#define WBS_STRIDE 132
#define WBS_TILE   (WBK * WBS_STRIDE)
#define WC_STRIDE  132
#define WSMEM_BYTES (WBM * WC_STRIDE * 4)

template <int KDIM, int N, bool PHASE1>
__global__ __launch_bounds__(256, 2)
void moe_gemm_wmma(const float* __restrict__ Aglob,
                   const float* __restrict__ Bglob,
                   const float* __restrict__ biasg,
                   float* __restrict__ outg) {
    if (g_use_tc) return;
    int e   = blockIdx.z;
    int cnt = g_count[e];
    int m0  = blockIdx.y * WBM;
    if (m0 >= cnt) return;
    int n0  = blockIdx.x * WBN;

    extern __shared__ __align__(16) float sbuf[];
    float* As = sbuf;
    float* Bs = sbuf + 2 * WAS_TILE;

    const float* Bp    = Bglob + (size_t)e * KDIM * N + n0;
    const float* hrows = g_h + (size_t)g_offset[e] * (size_t)KDIM;

    int tid = threadIdx.x;
    int acol = (tid & 3) * 4;
    int arow[2];
    const float* aptr[2];
#pragma unroll
    for (int i = 0; i < 2; i++) {
        int r = (tid >> 2) + i * 64;
        arow[i] = r;
        int m = m0 + r;
        if (m < cnt)
            aptr[i] = (PHASE1 ? Aglob + (size_t)g_tok[e][m] * KDIM
                              : hrows + (size_t)m * KDIM) + acol;
        else aptr[i] = nullptr;
    }
    int bkr  = tid >> 5;
    int bnc  = (tid & 31) * 4;
    const float* bptr = Bp + (size_t)bkr * N + bnc;

    float4 areg[2], breg[2];
    auto ldG = [&](int kt) {
#pragma unroll
        for (int i = 0; i < 2; i++)
            areg[i] = aptr[i] ? *(const float4*)(aptr[i] + kt * WBK)
                              : make_float4(0.f, 0.f, 0.f, 0.f);
#pragma unroll
        for (int i = 0; i < 2; i++)
            breg[i] = *(const float4*)(bptr + (size_t)(kt * WBK + i * 8) * N);
    };
    auto stS = [&](int buf) {
        float* a = As + buf * WAS_TILE;
        float* b = Bs + buf * WBS_TILE;
#pragma unroll
        for (int i = 0; i < 2; i++) {
            float4 v = make_float4(wmma::__float_to_tf32(areg[i].x),
                                   wmma::__float_to_tf32(areg[i].y),
                                   wmma::__float_to_tf32(areg[i].z),
                                   wmma::__float_to_tf32(areg[i].w));
            *(float4*)(a + arow[i] * WAS_STRIDE + acol) = v;
        }
#pragma unroll
        for (int i = 0; i < 2; i++) {
            float4 v = make_float4(wmma::__float_to_tf32(breg[i].x),
                                   wmma::__float_to_tf32(breg[i].y),
                                   wmma::__float_to_tf32(breg[i].z),
                                   wmma::__float_to_tf32(breg[i].w));
            *(float4*)(b + (bkr + i * 8) * WBS_STRIDE + bnc) = v;
        }
    };

    int warp = tid >> 5;
    int wm   = (warp >> 1) * 32;
    int wn   = (warp & 1) * 64;

    wmma::fragment<wmma::accumulator, 16, 16, 8, float> c[2][4];
#pragma unroll
    for (int i = 0; i < 2; i++)
#pragma unroll
        for (int j = 0; j < 4; j++) wmma::fill_fragment(c[i][j], 0.0f);

    auto compute = [&](int buf) {
        const float* a = As + buf * WAS_TILE;
        const float* b = Bs + buf * WBS_TILE;
#pragma unroll
        for (int kk = 0; kk < WBK; kk += 8) {
            wmma::fragment<wmma::matrix_a, 16, 16, 8, wmma::precision::tf32, wmma::row_major> af[2];
            wmma::fragment<wmma::matrix_b, 16, 16, 8, wmma::precision::tf32, wmma::row_major> bf[4];
#pragma unroll
            for (int i = 0; i < 2; i++)
                wmma::load_matrix_sync(af[i], a + (wm + i * 16) * WAS_STRIDE + kk, WAS_STRIDE);
#pragma unroll
            for (int j = 0; j < 4; j++)
                wmma::load_matrix_sync(bf[j], b + kk * WBS_STRIDE + wn + j * 16, WBS_STRIDE);
#pragma unroll
            for (int i = 0; i < 2; i++)
#pragma unroll
                for (int j = 0; j < 4; j++)
                    wmma::mma_sync(c[i][j], af[i], bf[j], c[i][j]);
        }
    };

    constexpr int KT = KDIM / WBK;
    ldG(0);
    stS(0);
    __syncthreads();
#pragma unroll 1
    for (int kt = 0; kt < KT; kt++) {
        int cur = kt & 1;
        if (kt + 1 < KT) ldG(kt + 1);
        compute(cur);
        if (kt + 1 < KT) {
            stS((kt + 1) & 1);
            __syncthreads();
        }
    }
    __syncthreads();

#pragma unroll
    for (int i = 0; i < 2; i++)
#pragma unroll
        for (int j = 0; j < 4; j++)
            wmma::store_matrix_sync(sbuf + (wm + i * 16) * WC_STRIDE + wn + j * 16,
                                    c[i][j], WC_STRIDE, wmma::mem_row_major);
    __syncthreads();

    const float* bias = biasg + (size_t)e * N + n0;
    if (PHASE1) {
        float* hb = g_h + (size_t)g_offset[e] * (size_t)N;
#pragma unroll
        for (int i = 0; i < 16; i++) {
            int f  = tid + i * 256;
            int r  = f >> 5;
            int cc = (f & 31) * 4;
            int m  = m0 + r;
            if (m < cnt) {
                const float* cs = sbuf + r * WC_STRIDE + cc;
                float4 bv = *(const float4*)(bias + cc);
                float4 v;
                v.x = fmaxf(cs[0] + bv.x, 0.f);
                v.y = fmaxf(cs[1] + bv.y, 0.f);
                v.z = fmaxf(cs[2] + bv.z, 0.f);
                v.w = fmaxf(cs[3] + bv.w, 0.f);
                *(float4*)(hb + (size_t)m * N + n0 + cc) = v;
            }
        }
    } else {
#pragma unroll
        for (int i = 0; i < 16; i++) {
            int f  = tid + i * 256;
            int r  = f >> 5;
            int cc = (f & 31) * 4;
            int m  = m0 + r;
            if (m < cnt) {
                const float* cs = sbuf + r * WC_STRIDE + cc;
                float w   = g_w[e][m];
                int   tok = g_tok[e][m];
                float* op = outg + (size_t)tok * N + n0 + cc;
                const float* bv = bias + cc;
                atomicAdd(op + 0, w * (cs[0] + bv[0]));
                atomicAdd(op + 1, w * (cs[1] + bv[1]));
                atomicAdd(op + 2, w * (cs[2] + bv[2]));
                atomicAdd(op + 3, w * (cs[3] + bv[3]));
            }
        }
    }
}

// ===============================================================
// Path B: tcgen05 SS tf32, 128(feat) x 256(tok) x 32 tiles.
// ===============================================================
__device__ __forceinline__ uint32_t smem_to_u32(const void* p) {
    uint32_t a;
    asm("{ .reg .u64 t; cvta.to.shared.u64 t, %1; cvt.u32.u64 %0, t; }" : "=r"(a) : "l"(p));
    return a;
}
__device__ __forceinline__ uint32_t elect_one_pred() {
    uint32_t p;
    asm volatile("{\n\t.reg .pred p;\n\telect.sync _|p, 0xFFFFFFFF;\n\tselp.b32 %0, 1, 0, p;\n\t}" : "=r"(p));
    return p;
}
#define MBARRIER_INIT(addr, cnt) \
    asm volatile("mbarrier.init.shared.b64 [%0], %1;" :: "r"((uint32_t)(addr)), "r"((uint32_t)(cnt)) : "memory")
#define MBARRIER_WAIT_PARITY(mbar, par) do {                                   \
    uint32_t _m = (uint32_t)(mbar); uint32_t _p = (uint32_t)(par);             \
    asm volatile("{\n\t.reg .pred P1;\n\t"                                     \
        "WAIT_LOOP_%=:\n\t"                                                    \
        "mbarrier.try_wait.parity.acquire.cta.shared::cta.b64 P1, [%0], %1, 0x989680;\n\t" \
        "@P1 bra.uni WAIT_DONE_%=;\n\t"                                        \
        "bra.uni WAIT_LOOP_%=;\n\t"                                            \
        "WAIT_DONE_%=:\n\t}" :: "r"(_m), "r"(_p) : "memory");                  \
} while (0)
#define FENCE_ASYNC() asm volatile("fence.proxy.async.shared::cta;" ::: "memory")

static __device__ __forceinline__ uint64_t make_desc_sw128(uint32_t addr) {
    const uint64_t base = (uint64_t(2) << 61) | (uint64_t(1) << 46)
                        | (uint64_t(64) << 32) | (uint64_t(1) << 16);
    return base | ((uint64_t)(addr >> 4) & 0x3FFF);
}
__device__ __forceinline__ uint32_t swz(uint32_t off) { return off ^ ((off >> 3) & 0x70); }
__device__ __forceinline__ float to_tf32(float x) {
    float y; asm("cvt.rna.tf32.f32 %0, %1;" : "=f"(y) : "f"(x)); return y;
}

// N=256 tokens: (256/8)<<17 ; M=128 ; dtype F32, a/b tf32
#define IDESC_TF32_N256 ((1u << 4) | (2u << 7) | (2u << 10) | (32u << 17) | (8u << 24))
#define BNT 256
#define SOFF_TMEM 0
#define SOFF_MB0  16
#define SOFF_MB1  24
#define SOFF_MBD  32
#define SOFF_A    1024
#define ABUF_SZ   16384                        /* 128 x 32 x 4 */
#define SOFF_B    (SOFF_A + 2 * ABUF_SZ)
#define BBUF_SZ   32768                        /* 256 x 32 x 4 */
#define TC_SMEM   (SOFF_B + 2 * BBUF_SZ)       /* 99328 */

template <int KDIM, int NFEAT, bool PHASE1>
__global__ __launch_bounds__(256, 2)
void moe_mma_tc(const float* __restrict__ act,
                const float* __restrict__ Wt,
                const float* __restrict__ biasg,
                float* __restrict__ outg) {
#if TC_PATH
    int e   = blockIdx.z;
    int cnt = g_count[e];
    int m0  = blockIdx.y * BNT;
    if (m0 >= cnt) return;
    int f0  = blockIdx.x * 128;
    int goff = g_offset[e];

    extern __shared__ __align__(1024) char smem[];
    uint32_t sb  = smem_to_u32(smem);
    int tid = threadIdx.x, wid = tid >> 5, lane = tid & 31;

    if (tid == 0) {
        MBARRIER_INIT(sb + SOFF_MB0, 1);
        MBARRIER_INIT(sb + SOFF_MB1, 1);
        MBARRIER_INIT(sb + SOFF_MBD, 1);
    }
    if (wid == 0)
        asm volatile("tcgen05.alloc.cta_group::1.sync.aligned.shared::cta.b32 [%0], %1;"
            :: "r"(sb + SOFF_TMEM), "r"(256u) : "memory");
    __syncthreads();
    uint32_t tmem;
    asm volatile("ld.shared.b32 %0, [%1];" : "=r"(tmem) : "r"(sb + SOFF_TMEM));
    if (wid == 0)
        asm volatile("tcgen05.relinquish_alloc_permit.cta_group::1.sync.aligned;");

    // ---- A (weights [KDIM][NFEAT], 4x4 register transpose) ----
    int kg = tid & 7, hg = tid >> 3;
    const float* aptr = Wt + (size_t)e * KDIM * NFEAT + (size_t)(4 * kg) * NFEAT + f0 + 4 * hg;
    uint32_t aoff[4];
#pragma unroll
    for (int j = 0; j < 4; j++) aoff[j] = swz((4 * hg + j) * 128 + 16 * kg);

    // ---- B (activations, 256 rows x 32 floats/step): u32 offsets + mask ----
    int q = tid & 7, rbase = tid >> 3;
    const char* bbase = (const char*)(PHASE1 ? act : g_h);
    uint32_t brow[8];
    unsigned bvalid = 0;
#pragma unroll
    for (int i = 0; i < 8; i++) {
        int r = rbase + i * 32;
        int m = m0 + r;
        if (m < cnt) {
            bvalid |= 1u << i;
            uint32_t row = PHASE1 ? (uint32_t)g_tok[e][m] : (uint32_t)(goff + m);
            brow[i] = row * (uint32_t)(KDIM * 4) + 16u * q;
        } else brow[i] = 0;
    }
    uint32_t boff[8];
#pragma unroll
    for (int i = 0; i < 8; i++) boff[i] = swz((rbase + i * 32) * 128 + 16 * q);

    float4 areg[4], breg[8];
    auto ldG = [&](int kt) {
        const float* ap = aptr + (size_t)(kt * 32) * NFEAT;
#pragma unroll
        for (int i = 0; i < 4; i++) areg[i] = *(const float4*)(ap + (size_t)i * NFEAT);
#pragma unroll
        for (int i = 0; i < 8; i++)
            breg[i] = (bvalid >> i & 1) ? *(const float4*)(bbase + brow[i] + (uint32_t)kt * 128u)
                                        : make_float4(0.f, 0.f, 0.f, 0.f);
    };
    auto stS = [&](int b) {
        uint32_t abo = SOFF_A + b * ABUF_SZ;
        uint32_t bbo = SOFF_B + b * BBUF_SZ;
        float c0[4] = {areg[0].x, areg[0].y, areg[0].z, areg[0].w};
        float c1[4] = {areg[1].x, areg[1].y, areg[1].z, areg[1].w};
        float c2[4] = {areg[2].x, areg[2].y, areg[2].z, areg[2].w};
        float c3[4] = {areg[3].x, areg[3].y, areg[3].z, areg[3].w};
#pragma unroll
        for (int j = 0; j < 4; j++) {
            float4 v = make_float4(to_tf32(c0[j]), to_tf32(c1[j]),
                                   to_tf32(c2[j]), to_tf32(c3[j]));
            *(float4*)(smem + abo + aoff[j]) = v;
        }
#pragma unroll
        for (int i = 0; i < 8; i++) {
            float4 v = make_float4(to_tf32(breg[i].x), to_tf32(breg[i].y),
                                   to_tf32(breg[i].z), to_tf32(breg[i].w));
            *(float4*)(smem + bbo + boff[i]) = v;
        }
    };

    constexpr int KT = KDIM / 32;
    uint64_t adb[2] = { make_desc_sw128(sb + SOFF_A),
                        make_desc_sw128(sb + SOFF_A + ABUF_SZ) };
    uint64_t bdb[2] = { make_desc_sw128(sb + SOFF_B),
                        make_desc_sw128(sb + SOFF_B + BBUF_SZ) };
    int ph[2] = {0, 0};

    ldG(0);
#pragma unroll 1
    for (int kt = 0; kt < KT; kt++) {
        int b = kt & 1;
        if (kt >= 2) { MBARRIER_WAIT_PARITY(sb + (b ? SOFF_MB1 : SOFF_MB0), ph[b]); ph[b] ^= 1; }
        stS(b);
        FENCE_ASYNC();
        __syncthreads();
        if (kt + 1 < KT) ldG(kt + 1);
        if (wid == 0 && elect_one_pred()) {
#pragma unroll
            for (int s = 0; s < 4; s++) {
                uint32_t en = (kt == 0 && s == 0) ? 0u : 1u;
                asm volatile("{\n\t.reg .pred p;\n\tsetp.ne.u32 p, %4, 0;\n\t"
                    "tcgen05.mma.cta_group::1.kind::tf32 [%0], %1, %2, %3, {%5,%5,%5,%5}, p;\n\t}"
                    :: "r"(tmem), "l"(adb[b] + s * 2), "l"(bdb[b] + s * 2),
                       "r"((uint32_t)IDESC_TF32_N256), "r"(en), "r"(0u) : "memory");
            }
            asm volatile("tcgen05.commit.cta_group::1.mbarrier::arrive::one.shared::cluster.b64 [%0];"
                :: "r"(sb + (b ? SOFF_MB1 : SOFF_MB0)) : "memory");
        }
    }
    if (wid == 0 && elect_one_pred())
        asm volatile("tcgen05.commit.cta_group::1.mbarrier::arrive::one.shared::cluster.b64 [%0];"
            :: "r"(sb + SOFF_MBD) : "memory");
    MBARRIER_WAIT_PARITY(sb + SOFF_MBD, 0);
    asm volatile("tcgen05.fence::after_thread_sync;" ::: "memory");

    // ---- epilogue: warp (wid&3) = feature subpartition, (wid>>2) = token half
    int sub  = wid & 3;
    int half = wid >> 2;
    int h    = f0 + sub * 32 + lane;
    float bias = biasg[(size_t)e * NFEAT + h];
#pragma unroll
    for (int c = 0; c < 4; c++) {
        int colbase = half * 128 + c * 32;
        uint32_t r[32];
        asm volatile("tcgen05.ld.sync.aligned.32x32b.x32.b32 "
            "{%0,%1,%2,%3,%4,%5,%6,%7,%8,%9,%10,%11,%12,%13,%14,%15,"
            "%16,%17,%18,%19,%20,%21,%22,%23,%24,%25,%26,%27,%28,%29,%30,%31}, [%32];"
            : "=r"(r[0]),"=r"(r[1]),"=r"(r[2]),"=r"(r[3]),"=r"(r[4]),"=r"(r[5]),"=r"(r[6]),"=r"(r[7]),
              "=r"(r[8]),"=r"(r[9]),"=r"(r[10]),"=r"(r[11]),"=r"(r[12]),"=r"(r[13]),"=r"(r[14]),"=r"(r[15]),
              "=r"(r[16]),"=r"(r[17]),"=r"(r[18]),"=r"(r[19]),"=r"(r[20]),"=r"(r[21]),"=r"(r[22]),"=r"(r[23]),
              "=r"(r[24]),"=r"(r[25]),"=r"(r[26]),"=r"(r[27]),"=r"(r[28]),"=r"(r[29]),"=r"(r[30]),"=r"(r[31])
            : "r"(tmem + colbase));
        asm volatile("tcgen05.wait::ld.sync.aligned;" ::: "memory");
#pragma unroll
        for (int t = 0; t < 32; t++) {
            int m = m0 + colbase + t;
            if (m < cnt) {
                float v = __uint_as_float(r[t]) + bias;
                if (PHASE1) {
                    v = fmaxf(v, 0.f);
                    g_h[(size_t)(goff + m) * NFEAT + h] = v;
                } else {
                    // exactly 2 atomic adds per output element -> deterministic
                    atomicAdd(&outg[(size_t)g_tok[e][m] * NFEAT + h], g_w[e][m] * v);
                }
            }
        }
    }
    __syncthreads();
    if (wid == 0)
        asm volatile("tcgen05.dealloc.cta_group::1.sync.aligned.b32 %0, %1;"
            :: "r"(tmem), "r"(256u));
#endif  // TC_PATH
}

// ---------------------------------------------------------------
extern "C" void kernel_launch(void* const* d_in, const int* in_sizes, int n_in,
                              void* d_out, int out_size) {
    const float* xs = (const float*)d_in[0];
    // d_in[1] = top_k (int32 scalar) -- fixed at 2 for this problem
    const float* Wg = (const float*)d_in[2];
    const float* W1 = (const float*)d_in[3];
    const float* b1 = (const float*)d_in[4];
    const float* W2 = (const float*)d_in[5];
    const float* b2 = (const float*)d_in[6];
    float* out = (float*)d_out;

    cudaFuncSetAttribute(moe_gemm_wmma<IDIM_, HIDDEN_, true>,
                         cudaFuncAttributeMaxDynamicSharedMemorySize, WSMEM_BYTES);
    cudaFuncSetAttribute(moe_gemm_wmma<HIDDEN_, IDIM_, false>,
                         cudaFuncAttributeMaxDynamicSharedMemorySize, WSMEM_BYTES);
    cudaFuncSetAttribute(moe_mma_tc<IDIM_, HIDDEN_, true>,
                         cudaFuncAttributeMaxDynamicSharedMemorySize, TC_SMEM);
    cudaFuncSetAttribute(moe_mma_tc<HIDDEN_, IDIM_, false>,
                         cudaFuncAttributeMaxDynamicSharedMemorySize, TC_SMEM);

    cudaMemsetAsync(out, 0, (size_t)T_TOK * IDIM_ * sizeof(float));
    probe_kernel<<<1, 32>>>();
    router_kernel<<<(T_TOK * 32 + 1023) / 1024, 1024>>>(xs, Wg);
    compute_offsets_kernel<<<1, 32>>>();

    // Path A (self-disables when g_use_tc == 1)
    moe_gemm_wmma<IDIM_, HIDDEN_, true>
        <<<dim3(HIDDEN_ / WBN, T_TOK / WBM, NEXP), 256, WSMEM_BYTES>>>(xs, W1, b1, nullptr);
    // Path B (empty body unless arch-specific cubin is loaded)
    moe_mma_tc<IDIM_, HIDDEN_, true>
        <<<dim3(HIDDEN_ / 128, T_TOK / BNT, NEXP), 256, TC_SMEM>>>(xs, W1, b1, nullptr);

    moe_gemm_wmma<HIDDEN_, IDIM_, false>
        <<<dim3(IDIM_ / WBN, T_TOK / WBM, NEXP), 256, WSMEM_BYTES>>>(nullptr, W2, b2, out);
    moe_mma_tc<HIDDEN_, IDIM_, false>
        <<<dim3(IDIM_ / 128, T_TOK / BNT, NEXP), 256, TC_SMEM>>>(nullptr, W2, b2, out);
}

// round 17
// speedup vs baseline: 1.4970x; 1.4970x over previous
#include <cuda_runtime.h>
#include <cuda_bf16.h>
#include <mma.h>
#include <cstdint>

using namespace nvcuda;

#define T_TOK   2048
#define IDIM_   1024
#define HIDDEN_ 4096
#define NEXP    8

// Feature gate: tcgen05 PTX is only legal when the device pass targets an
// arch-specific ('a') Blackwell target. compute_103 (no 'a') must compile it out.
#if !defined(__CUDA_ARCH__) || defined(__CUDA_ARCH_FEAT_SM103_ALL) || \
    defined(__CUDA_ARCH_FEAT_SM100_ALL) || defined(__CUDA_ARCH_SPECIFIC__)
#define TC_PATH 1
#else
#define TC_PATH 0
#endif

// ---- device scratch (allocation-free: static device globals) ----
__device__ int   g_count[NEXP];
__device__ int   g_offset[NEXP];
__device__ int   g_tok[NEXP][T_TOK];
__device__ float g_w[NEXP][T_TOK];
__device__ float g_h[(size_t)2 * T_TOK * HIDDEN_];      // compacted hidden rows (tf32-rounded)
__device__ float g_x[(size_t)T_TOK * IDIM_];            // tf32-rounded activations
__device__ float g_w1t[(size_t)NEXP * HIDDEN_ * IDIM_]; // W1^T [E][H][K], rounded
__device__ float g_w2t[(size_t)NEXP * IDIM_ * HIDDEN_]; // W2^T [E][D][H], rounded
__device__ int   g_use_tc;

__device__ __forceinline__ float to_tf32(float x) {
    float y; asm("cvt.rna.tf32.f32 %0, %1;" : "=f"(y) : "f"(x)); return y;
}

// ---------------------------------------------------------------
__global__ void probe_kernel() {
    if (threadIdx.x == 0) {
#if TC_PATH && defined(__CUDA_ARCH__)
        g_use_tc = 1;
#else
        g_use_tc = 0;
#endif
    }
    if (threadIdx.x < NEXP) g_count[threadIdx.x] = 0;
}

// pre-round activations (tc path only)
__global__ void round_x_kernel(const float* __restrict__ xs) {
    if (!g_use_tc) return;
    int i = blockIdx.x * blockDim.x + threadIdx.x;
    const float4* src = (const float4*)xs;
    float4* dst = (float4*)g_x;
    if (i < T_TOK * IDIM_ / 4) {
        float4 v = src[i];
        dst[i] = make_float4(to_tf32(v.x), to_tf32(v.y), to_tf32(v.z), to_tf32(v.w));
    }
}

// W [E][K][N] -> Wt [E][N][K] with tf32 rounding (tc path only).
// NOTE: destination selected by template INSIDE device code — passing a
// __device__ symbol as a host-side kernel arg silently resolves to the host
// shadow object (ATS makes the store succeed into host memory!).
template <bool FIRST>
__global__ void transpose_w_kernel(const float* __restrict__ W, int K, int N) {
    if (!g_use_tc) return;
    float* Wt = FIRST ? g_w1t : g_w2t;
    __shared__ float t[32][33];
    int e  = blockIdx.z;
    int n0 = blockIdx.x * 32, k0 = blockIdx.y * 32;
    const float* Wp = W + (size_t)e * K * N;
    float* Wtp = Wt + (size_t)e * K * N;
    int tx = threadIdx.x, ty = threadIdx.y;
#pragma unroll
    for (int i = 0; i < 4; i++)
        t[ty * 4 + i][tx] = Wp[(size_t)(k0 + ty * 4 + i) * N + n0 + tx];
    __syncthreads();
#pragma unroll
    for (int i = 0; i < 4; i++)
        Wtp[(size_t)(n0 + ty * 4 + i) * K + k0 + tx] = to_tf32(t[tx][ty * 4 + i]);
}

__global__ void router_kernel(const float* __restrict__ xs,
                              const float* __restrict__ Wg) {
    int gwarp = (blockIdx.x * blockDim.x + threadIdx.x) >> 5;
    int lane  = threadIdx.x & 31;
    if (gwarp >= T_TOK) return;
    const float4* x = (const float4*)(xs + (size_t)gwarp * IDIM_);
    float acc[NEXP];
#pragma unroll
    for (int e = 0; e < NEXP; e++) acc[e] = 0.f;
    for (int k = lane; k < IDIM_ / 4; k += 32) {
        float4 xv = x[k];
#pragma unroll
        for (int e = 0; e < NEXP; e++) {
            const float4 wv = ((const float4*)(Wg + e * IDIM_))[k];
            acc[e] += xv.x * wv.x + xv.y * wv.y + xv.z * wv.z + xv.w * wv.w;
        }
    }
#pragma unroll
    for (int e = 0; e < NEXP; e++)
#pragma unroll
        for (int off = 16; off; off >>= 1)
            acc[e] += __shfl_xor_sync(0xffffffffu, acc[e], off);
    if (lane == 0) {
        int i0 = 0; float v0 = acc[0];
#pragma unroll
        for (int e = 1; e < NEXP; e++) if (acc[e] > v0) { v0 = acc[e]; i0 = e; }
        int i1 = -1; float v1 = -3.4e38f;
#pragma unroll
        for (int e = 0; e < NEXP; e++) if (e != i0 && acc[e] > v1) { v1 = acc[e]; i1 = e; }
        float e1 = expf(v1 - v0);
        float s  = 1.0f + e1;
        int s0 = atomicAdd(&g_count[i0], 1);
        g_tok[i0][s0] = gwarp; g_w[i0][s0] = 1.0f / s;
        int s1 = atomicAdd(&g_count[i1], 1);
        g_tok[i1][s1] = gwarp; g_w[i1][s1] = e1 / s;
    }
}

__global__ void compute_offsets_kernel() {
    if (threadIdx.x == 0) {
        int off = 0;
#pragma unroll
        for (int e = 0; e < NEXP; e++) { g_offset[e] = off; off += g_count[e]; }
    }
}

// ===============================================================
// Path A: wmma tf32 fallback (self-disables when g_use_tc == 1).
// ===============================================================
#define WBM 128
#define WBN 128
#define WBK 16
#define WAS_STRIDE 20
#define WAS_TILE   (WBM * WAS_STRIDE)
#define WBS_STRIDE 132
#define WBS_TILE   (WBK * WBS_STRIDE)
#define WC_STRIDE  132
#define WSMEM_BYTES (WBM * WC_STRIDE * 4)

template <int KDIM, int N, bool PHASE1>
__global__ __launch_bounds__(256, 2)
void moe_gemm_wmma(const float* __restrict__ Aglob,
                   const float* __restrict__ Bglob,
                   const float* __restrict__ biasg,
                   float* __restrict__ outg) {
    if (g_use_tc) return;
    int e   = blockIdx.z;
    int cnt = g_count[e];
    int m0  = blockIdx.y * WBM;
    if (m0 >= cnt) return;
    int n0  = blockIdx.x * WBN;

    extern __shared__ __align__(16) float sbuf[];
    float* As = sbuf;
    float* Bs = sbuf + 2 * WAS_TILE;

    const float* Bp    = Bglob + (size_t)e * KDIM * N + n0;
    const float* hrows = g_h + (size_t)g_offset[e] * (size_t)KDIM;

    int tid = threadIdx.x;
    int acol = (tid & 3) * 4;
    int arow[2];
    const float* aptr[2];
#pragma unroll
    for (int i = 0; i < 2; i++) {
        int r = (tid >> 2) + i * 64;
        arow[i] = r;
        int m = m0 + r;
        if (m < cnt)
            aptr[i] = (PHASE1 ? Aglob + (size_t)g_tok[e][m] * KDIM
                              : hrows + (size_t)m * KDIM) + acol;
        else aptr[i] = nullptr;
    }
    int bkr  = tid >> 5;
    int bnc  = (tid & 31) * 4;
    const float* bptr = Bp + (size_t)bkr * N + bnc;

    float4 areg[2], breg[2];
    auto ldG = [&](int kt) {
#pragma unroll
        for (int i = 0; i < 2; i++)
            areg[i] = aptr[i] ? *(const float4*)(aptr[i] + kt * WBK)
                              : make_float4(0.f, 0.f, 0.f, 0.f);
#pragma unroll
        for (int i = 0; i < 2; i++)
            breg[i] = *(const float4*)(bptr + (size_t)(kt * WBK + i * 8) * N);
    };
    auto stS = [&](int buf) {
        float* a = As + buf * WAS_TILE;
        float* b = Bs + buf * WBS_TILE;
#pragma unroll
        for (int i = 0; i < 2; i++) {
            float4 v = make_float4(wmma::__float_to_tf32(areg[i].x),
                                   wmma::__float_to_tf32(areg[i].y),
                                   wmma::__float_to_tf32(areg[i].z),
                                   wmma::__float_to_tf32(areg[i].w));
            *(float4*)(a + arow[i] * WAS_STRIDE + acol) = v;
        }
#pragma unroll
        for (int i = 0; i < 2; i++) {
            float4 v = make_float4(wmma::__float_to_tf32(breg[i].x),
                                   wmma::__float_to_tf32(breg[i].y),
                                   wmma::__float_to_tf32(breg[i].z),
                                   wmma::__float_to_tf32(breg[i].w));
            *(float4*)(b + (bkr + i * 8) * WBS_STRIDE + bnc) = v;
        }
    };

    int warp = tid >> 5;
    int wm   = (warp >> 1) * 32;
    int wn   = (warp & 1) * 64;

    wmma::fragment<wmma::accumulator, 16, 16, 8, float> c[2][4];
#pragma unroll
    for (int i = 0; i < 2; i++)
#pragma unroll
        for (int j = 0; j < 4; j++) wmma::fill_fragment(c[i][j], 0.0f);

    auto compute = [&](int buf) {
        const float* a = As + buf * WAS_TILE;
        const float* b = Bs + buf * WBS_TILE;
#pragma unroll
        for (int kk = 0; kk < WBK; kk += 8) {
            wmma::fragment<wmma::matrix_a, 16, 16, 8, wmma::precision::tf32, wmma::row_major> af[2];
            wmma::fragment<wmma::matrix_b, 16, 16, 8, wmma::precision::tf32, wmma::row_major> bf[4];
#pragma unroll
            for (int i = 0; i < 2; i++)
                wmma::load_matrix_sync(af[i], a + (wm + i * 16) * WAS_STRIDE + kk, WAS_STRIDE);
#pragma unroll
            for (int j = 0; j < 4; j++)
                wmma::load_matrix_sync(bf[j], b + kk * WBS_STRIDE + wn + j * 16, WBS_STRIDE);
#pragma unroll
            for (int i = 0; i < 2; i++)
#pragma unroll
                for (int j = 0; j < 4; j++)
                    wmma::mma_sync(c[i][j], af[i], bf[j], c[i][j]);
        }
    };

    constexpr int KT = KDIM / WBK;
    ldG(0);
    stS(0);
    __syncthreads();
#pragma unroll 1
    for (int kt = 0; kt < KT; kt++) {
        int cur = kt & 1;
        if (kt + 1 < KT) ldG(kt + 1);
        compute(cur);
        if (kt + 1 < KT) {
            stS((kt + 1) & 1);
            __syncthreads();
        }
    }
    __syncthreads();

#pragma unroll
    for (int i = 0; i < 2; i++)
#pragma unroll
        for (int j = 0; j < 4; j++)
            wmma::store_matrix_sync(sbuf + (wm + i * 16) * WC_STRIDE + wn + j * 16,
                                    c[i][j], WC_STRIDE, wmma::mem_row_major);
    __syncthreads();

    const float* bias = biasg + (size_t)e * N + n0;
    if (PHASE1) {
        float* hb = g_h + (size_t)g_offset[e] * (size_t)N;
#pragma unroll
        for (int i = 0; i < 16; i++) {
            int f  = tid + i * 256;
            int r  = f >> 5;
            int cc = (f & 31) * 4;
            int m  = m0 + r;
            if (m < cnt) {
                const float* cs = sbuf + r * WC_STRIDE + cc;
                float4 bv = *(const float4*)(bias + cc);
                float4 v;
                v.x = fmaxf(cs[0] + bv.x, 0.f);
                v.y = fmaxf(cs[1] + bv.y, 0.f);
                v.z = fmaxf(cs[2] + bv.z, 0.f);
                v.w = fmaxf(cs[3] + bv.w, 0.f);
                *(float4*)(hb + (size_t)m * N + n0 + cc) = v;
            }
        }
    } else {
#pragma unroll
        for (int i = 0; i < 16; i++) {
            int f  = tid + i * 256;
            int r  = f >> 5;
            int cc = (f & 31) * 4;
            int m  = m0 + r;
            if (m < cnt) {
                const float* cs = sbuf + r * WC_STRIDE + cc;
                float w   = g_w[e][m];
                int   tok = g_tok[e][m];
                float* op = outg + (size_t)tok * N + n0 + cc;
                const float* bv = bias + cc;
                atomicAdd(op + 0, w * (cs[0] + bv[0]));
                atomicAdd(op + 1, w * (cs[1] + bv[1]));
                atomicAdd(op + 2, w * (cs[2] + bv[2]));
                atomicAdd(op + 3, w * (cs[3] + bv[3]));
            }
        }
    }
}

// ===============================================================
// Path B: tcgen05 SS tf32, 128(feat) x 128(tok) x 32.
// R7 control flow (2-stage, single reg set, distance-1 prefetch)
// + pre-rounded pre-transposed operands -> copy-only stS.
// ===============================================================
__device__ __forceinline__ uint32_t smem_to_u32(const void* p) {
    uint32_t a;
    asm("{ .reg .u64 t; cvta.to.shared.u64 t, %1; cvt.u32.u64 %0, t; }" : "=r"(a) : "l"(p));
    return a;
}
__device__ __forceinline__ uint32_t elect_one_pred() {
    uint32_t p;
    asm volatile("{\n\t.reg .pred p;\n\telect.sync _|p, 0xFFFFFFFF;\n\tselp.b32 %0, 1, 0, p;\n\t}" : "=r"(p));
    return p;
}
#define MBARRIER_INIT(addr, cnt) \
    asm volatile("mbarrier.init.shared.b64 [%0], %1;" :: "r"((uint32_t)(addr)), "r"((uint32_t)(cnt)) : "memory")
#define MBARRIER_WAIT_PARITY(mbar, par) do {                                   \
    uint32_t _m = (uint32_t)(mbar); uint32_t _p = (uint32_t)(par);             \
    asm volatile("{\n\t.reg .pred P1;\n\t"                                     \
        "WAIT_LOOP_%=:\n\t"                                                    \
        "mbarrier.try_wait.parity.acquire.cta.shared::cta.b64 P1, [%0], %1, 0x989680;\n\t" \
        "@P1 bra.uni WAIT_DONE_%=;\n\t"                                        \
        "bra.uni WAIT_LOOP_%=;\n\t"                                            \
        "WAIT_DONE_%=:\n\t}" :: "r"(_m), "r"(_p) : "memory");                  \
} while (0)
#define FENCE_ASYNC() asm volatile("fence.proxy.async.shared::cta;" ::: "memory")

static __device__ __forceinline__ uint64_t make_desc_sw128(uint32_t addr) {
    const uint64_t base = (uint64_t(2) << 61) | (uint64_t(1) << 46)
                        | (uint64_t(64) << 32) | (uint64_t(1) << 16);
    return base | ((uint64_t)(addr >> 4) & 0x3FFF);
}
__device__ __forceinline__ uint32_t swz(uint32_t off) { return off ^ ((off >> 3) & 0x70); }

#define IDESC_TF32 ((1u << 4) | (2u << 7) | (2u << 10) | (16u << 17) | (8u << 24))
#define SOFF_TMEM 0
#define SOFF_MB0  16
#define SOFF_MB1  24
#define SOFF_MBD  32
#define SOFF_A    1024
#define ABUF_SZ   16384
#define SOFF_B    (SOFF_A + 2 * ABUF_SZ)
#define BBUF_SZ   16384
#define TC_SMEM   (SOFF_B + 2 * BBUF_SZ)   /* 66560 */

template <int KDIM, int NFEAT, bool PHASE1>
__global__ __launch_bounds__(256, 2)
void moe_mma_tc(const float* __restrict__ biasg,
                float* __restrict__ outg) {
#if TC_PATH
    int e   = blockIdx.z;
    int cnt = g_count[e];
    int m0  = blockIdx.y * 128;
    if (m0 >= cnt) return;
    int f0  = blockIdx.x * 128;
    int goff = g_offset[e];

    extern __shared__ __align__(1024) char smem[];
    uint32_t sb  = smem_to_u32(smem);
    int tid = threadIdx.x, wid = tid >> 5, lane = tid & 31;

    if (tid == 0) {
        MBARRIER_INIT(sb + SOFF_MB0, 1);
        MBARRIER_INIT(sb + SOFF_MB1, 1);
        MBARRIER_INIT(sb + SOFF_MBD, 1);
    }
    if (wid == 0)
        asm volatile("tcgen05.alloc.cta_group::1.sync.aligned.shared::cta.b32 [%0], %1;"
            :: "r"(sb + SOFF_TMEM), "r"(128u) : "memory");
    __syncthreads();
    uint32_t tmem;
    asm volatile("ld.shared.b32 %0, [%1];" : "=r"(tmem) : "r"(sb + SOFF_TMEM));
    if (wid == 0)
        asm volatile("tcgen05.relinquish_alloc_permit.cta_group::1.sync.aligned;");

    // unified mapping: q = tid&7 (16B lane in K), r = tid>>3, rows r+32i
    int q = tid & 7, r = tid >> 3;
    const char* abase = PHASE1 ? (const char*)g_w1t : (const char*)g_w2t;
    const char* bbase = PHASE1 ? (const char*)g_x   : (const char*)g_h;

    uint32_t arow[4], brow[4], soff[4];
    unsigned bvalid = 0;
#pragma unroll
    for (int i = 0; i < 4; i++) {
        int rr = r + 32 * i;
        arow[i] = (uint32_t)(e * NFEAT + f0 + rr) * (uint32_t)(KDIM * 4) + 16u * q;
        soff[i] = swz(rr * 128 + 16 * q);
        int m = m0 + rr;
        if (m < cnt) {
            bvalid |= 1u << i;
            uint32_t row = PHASE1 ? (uint32_t)g_tok[e][m] : (uint32_t)(goff + m);
            brow[i] = row * (uint32_t)(KDIM * 4) + 16u * q;
        } else brow[i] = 0;
    }

    float4 areg[4], breg[4];
    auto ldG = [&](int kt) {
        uint32_t ko = (uint32_t)kt * 128u;
#pragma unroll
        for (int i = 0; i < 4; i++)
            areg[i] = *(const float4*)(abase + arow[i] + ko);
#pragma unroll
        for (int i = 0; i < 4; i++)
            breg[i] = (bvalid >> i & 1) ? *(const float4*)(bbase + brow[i] + ko)
                                        : make_float4(0.f, 0.f, 0.f, 0.f);
    };
    auto stS = [&](int b) {
        char* ab = smem + SOFF_A + b * ABUF_SZ;
        char* bb = smem + SOFF_B + b * BBUF_SZ;
#pragma unroll
        for (int i = 0; i < 4; i++) *(float4*)(ab + soff[i]) = areg[i];
#pragma unroll
        for (int i = 0; i < 4; i++) *(float4*)(bb + soff[i]) = breg[i];
    };

    constexpr int KT = KDIM / 32;
    uint64_t adb[2] = { make_desc_sw128(sb + SOFF_A),
                        make_desc_sw128(sb + SOFF_A + ABUF_SZ) };
    uint64_t bdb[2] = { make_desc_sw128(sb + SOFF_B),
                        make_desc_sw128(sb + SOFF_B + BBUF_SZ) };
    int ph[2] = {0, 0};

    ldG(0);
#pragma unroll 1
    for (int kt = 0; kt < KT; kt++) {
        int b = kt & 1;
        if (kt >= 2) { MBARRIER_WAIT_PARITY(sb + (b ? SOFF_MB1 : SOFF_MB0), ph[b]); ph[b] ^= 1; }
        stS(b);
        FENCE_ASYNC();
        __syncthreads();
        if (kt + 1 < KT) ldG(kt + 1);
        if (wid == 0 && elect_one_pred()) {
#pragma unroll
            for (int s = 0; s < 4; s++) {
                uint32_t en = (kt == 0 && s == 0) ? 0u : 1u;
                asm volatile("{\n\t.reg .pred p;\n\tsetp.ne.u32 p, %4, 0;\n\t"
                    "tcgen05.mma.cta_group::1.kind::tf32 [%0], %1, %2, %3, {%5,%5,%5,%5}, p;\n\t}"
                    :: "r"(tmem), "l"(adb[b] + s * 2), "l"(bdb[b] + s * 2),
                       "r"((uint32_t)IDESC_TF32), "r"(en), "r"(0u) : "memory");
            }
            asm volatile("tcgen05.commit.cta_group::1.mbarrier::arrive::one.shared::cluster.b64 [%0];"
                :: "r"(sb + (b ? SOFF_MB1 : SOFF_MB0)) : "memory");
        }
    }
    if (wid == 0 && elect_one_pred())
        asm volatile("tcgen05.commit.cta_group::1.mbarrier::arrive::one.shared::cluster.b64 [%0];"
            :: "r"(sb + SOFF_MBD) : "memory");
    MBARRIER_WAIT_PARITY(sb + SOFF_MBD, 0);
    asm volatile("tcgen05.fence::after_thread_sync;" ::: "memory");

    // epilogue: warp (wid&3) = feature subpartition; wid<4 -> token chunks 0,1; else 2,3
    int sub = wid & 3;
    int h   = f0 + sub * 32 + lane;
    float bias = biasg[(size_t)e * NFEAT + h];
    int c0i = (wid < 4) ? 0 : 2;
#pragma unroll
    for (int c = c0i; c < c0i + 2; c++) {
        uint32_t rr[32];
        asm volatile("tcgen05.ld.sync.aligned.32x32b.x32.b32 "
            "{%0,%1,%2,%3,%4,%5,%6,%7,%8,%9,%10,%11,%12,%13,%14,%15,"
            "%16,%17,%18,%19,%20,%21,%22,%23,%24,%25,%26,%27,%28,%29,%30,%31}, [%32];"
            : "=r"(rr[0]),"=r"(rr[1]),"=r"(rr[2]),"=r"(rr[3]),"=r"(rr[4]),"=r"(rr[5]),"=r"(rr[6]),"=r"(rr[7]),
              "=r"(rr[8]),"=r"(rr[9]),"=r"(rr[10]),"=r"(rr[11]),"=r"(rr[12]),"=r"(rr[13]),"=r"(rr[14]),"=r"(rr[15]),
              "=r"(rr[16]),"=r"(rr[17]),"=r"(rr[18]),"=r"(rr[19]),"=r"(rr[20]),"=r"(rr[21]),"=r"(rr[22]),"=r"(rr[23]),
              "=r"(rr[24]),"=r"(rr[25]),"=r"(rr[26]),"=r"(rr[27]),"=r"(rr[28]),"=r"(rr[29]),"=r"(rr[30]),"=r"(rr[31])
            : "r"(tmem + c * 32));
        asm volatile("tcgen05.wait::ld.sync.aligned;" ::: "memory");
#pragma unroll
        for (int t = 0; t < 32; t++) {
            int m = m0 + c * 32 + t;
            if (m < cnt) {
                float v = __uint_as_float(rr[t]) + bias;
                if (PHASE1) {
                    v = to_tf32(fmaxf(v, 0.f));   // pre-round for phase2 copy-only path
                    g_h[(size_t)(goff + m) * NFEAT + h] = v;
                } else {
                    // exactly 2 atomic adds per output element -> deterministic
                    atomicAdd(&outg[(size_t)g_tok[e][m] * NFEAT + h], g_w[e][m] * v);
                }
            }
        }
    }
    __syncthreads();
    if (wid == 0)
        asm volatile("tcgen05.dealloc.cta_group::1.sync.aligned.b32 %0, %1;"
            :: "r"(tmem), "r"(128u));
#endif  // TC_PATH
}

// ---------------------------------------------------------------
extern "C" void kernel_launch(void* const* d_in, const int* in_sizes, int n_in,
                              void* d_out, int out_size) {
    const float* xs = (const float*)d_in[0];
    // d_in[1] = top_k (int32 scalar) -- fixed at 2 for this problem
    const float* Wg = (const float*)d_in[2];
    const float* W1 = (const float*)d_in[3];
    const float* b1 = (const float*)d_in[4];
    const float* W2 = (const float*)d_in[5];
    const float* b2 = (const float*)d_in[6];
    float* out = (float*)d_out;

    cudaFuncSetAttribute(moe_gemm_wmma<IDIM_, HIDDEN_, true>,
                         cudaFuncAttributeMaxDynamicSharedMemorySize, WSMEM_BYTES);
    cudaFuncSetAttribute(moe_gemm_wmma<HIDDEN_, IDIM_, false>,
                         cudaFuncAttributeMaxDynamicSharedMemorySize, WSMEM_BYTES);
    cudaFuncSetAttribute(moe_mma_tc<IDIM_, HIDDEN_, true>,
                         cudaFuncAttributeMaxDynamicSharedMemorySize, TC_SMEM);
    cudaFuncSetAttribute(moe_mma_tc<HIDDEN_, IDIM_, false>,
                         cudaFuncAttributeMaxDynamicSharedMemorySize, TC_SMEM);

    cudaMemsetAsync(out, 0, (size_t)T_TOK * IDIM_ * sizeof(float));
    probe_kernel<<<1, 32>>>();

    // prep (tc path only; self-disable otherwise)
    round_x_kernel<<<(T_TOK * IDIM_ / 4 + 255) / 256, 256>>>(xs);
    transpose_w_kernel<true>
        <<<dim3(HIDDEN_ / 32, IDIM_ / 32, NEXP), dim3(32, 8)>>>(W1, IDIM_, HIDDEN_);
    transpose_w_kernel<false>
        <<<dim3(IDIM_ / 32, HIDDEN_ / 32, NEXP), dim3(32, 8)>>>(W2, HIDDEN_, IDIM_);

    router_kernel<<<(T_TOK * 32 + 1023) / 1024, 1024>>>(xs, Wg);
    compute_offsets_kernel<<<1, 32>>>();

    // Path A (self-disables when g_use_tc == 1)
    moe_gemm_wmma<IDIM_, HIDDEN_, true>
        <<<dim3(HIDDEN_ / WBN, T_TOK / WBM, NEXP), 256, WSMEM_BYTES>>>(xs, W1, b1, nullptr);
    // Path B (empty body unless arch-specific cubin is loaded)
    moe_mma_tc<IDIM_, HIDDEN_, true>
        <<<dim3(HIDDEN_ / 128, T_TOK / 128, NEXP), 256, TC_SMEM>>>(b1, nullptr);

    moe_gemm_wmma<HIDDEN_, IDIM_, false>
        <<<dim3(IDIM_ / WBN, T_TOK / WBM, NEXP), 256, WSMEM_BYTES>>>(nullptr, W2, b2, out);
    moe_mma_tc<HIDDEN_, IDIM_, false>
        <<<dim3(IDIM_ / 128, T_TOK / 128, NEXP), 256, TC_SMEM>>>(b2, out);
}